// round 4
// baseline (speedup 1.0000x reference)
#include <cuda_runtime.h>
#include <math.h>
#include <stdint.h>

#define S_LEN 16384
#define I_DIM 64
#define R_DIM 2048
#define H_DIM 128
#define O_DIM 50
#define NBLK  128
#define ROWS_PER_BLK 16   // 128*16 = 2048
#define NTHR  512

// ---------------- device scratch (static; no allocations) ----------------
__device__ float g_h[2][R_DIM];
__device__ float g_states[(size_t)S_LEN * R_DIM];   // 134 MB
__device__ float g_Wc[O_DIM * R_DIM];               // folded fc2@fc1
__device__ float g_bc[O_DIM];                       // folded bias
__device__ unsigned g_tag[NBLK * 32];               // 1 tag per block, 128B apart; monotone

// packed f32x2 FMA: d = a*b + d (sm_100+; only reachable via PTX)
__device__ __forceinline__ void ffma2(uint64_t& d, uint64_t a, uint64_t b) {
    asm("fma.rn.f32x2 %0, %1, %2, %0;" : "+l"(d) : "l"(a), "l"(b));
}
__device__ __forceinline__ void st_release_u32(unsigned* p, unsigned v) {
    asm volatile("st.release.gpu.global.u32 [%0], %1;" :: "l"(p), "r"(v) : "memory");
}
__device__ __forceinline__ unsigned ld_acquire_u32(const unsigned* p) {
    unsigned v;
    asm volatile("ld.acquire.gpu.global.u32 %0, [%1];" : "=r"(v) : "l"(p) : "memory");
    return v;
}

// ---------------- persistent recurrence kernel ----------------
// W register-resident: block b owns rows [16b,16b+16); thread (grp,tg) owns
// rows 16b+4*grp..+3 as packed f32x2 column chunks {tg+128j}.
__global__ void __launch_bounds__(NTHR, 1) esn_kernel(
    const float* __restrict__ x,     // [S,64]
    const float* __restrict__ Win,   // [2048,64]
    const float* __restrict__ W)     // [2048,2048]
{
    __shared__ float4 hs4[R_DIM / 4];                 // staged h (8 KB)
    __shared__ float  psum2[ROWS_PER_BLK][4];

    const int tid  = threadIdx.x;
    const int lane = tid & 31;
    const int wrp  = tid >> 5;          // 0..15
    const int grp  = tid >> 7;          // 0..3
    const int tg   = tid & 127;         // 0..127
    const int wig  = wrp & 3;           // warp-in-group
    const int rbase = blockIdx.x * ROWS_PER_BLK;

    // W slice -> registers (64 floats/thread; 16 MB chip-wide, loaded once).
    uint64_t w2[4][8];
#pragma unroll
    for (int r = 0; r < 4; r++) {
        const ulonglong2* Wrow = (const ulonglong2*)(W + (size_t)(rbase + grp * 4 + r) * R_DIM);
#pragma unroll
        for (int j = 0; j < 4; j++) {
            ulonglong2 v = Wrow[tg + 128 * j];
            w2[r][2 * j]     = v.x;
            w2[r][2 * j + 1] = v.y;
        }
    }
    // Win column tg of my 4 rows -> registers (threads tg<64 fold xin into stage-1)
    float wr[4] = {0.f, 0.f, 0.f, 0.f};
    if (tg < I_DIM) {
#pragma unroll
        for (int r = 0; r < 4; r++)
            wr[r] = Win[(size_t)(rbase + grp * 4 + r) * I_DIM + tg];
    }

    // zero h0 (this block's rows), every launch
    if (tid < ROWS_PER_BLK) g_h[0][rbase + tid] = 0.0f;

    // per-warp monotone barrier counter, seeded from our own slot (replay-safe)
    unsigned bar_t = 0;
    if (wrp == 0) bar_t = g_tag[blockIdx.x * 32];

    // ---- distributed barrier: st.release own tag, poll all 128 with ld.acquire
#define GRID_BARRIER()                                                          \
    do {                                                                        \
        __syncthreads();                                                        \
        if (wrp == 0) {                                                         \
            bar_t += 1;                                                         \
            if (lane == 0) st_release_u32(&g_tag[blockIdx.x * 32], bar_t);      \
            bool ok;                                                            \
            do {                                                                \
                ok = true;                                                      \
                _Pragma("unroll")                                               \
                for (int j = 0; j < 4; j++) {                                   \
                    unsigned v = ld_acquire_u32(&g_tag[(lane + 32 * j) * 32]);  \
                    ok &= ((int)(v - bar_t) >= 0);                              \
                }                                                               \
            } while (!__all_sync(0xffffffffu, ok));                             \
        }                                                                       \
        __syncthreads();                                                        \
    } while (0)

    GRID_BARRIER();   // h0 published

    for (int t = 0; t < S_LEN; t++) {
        const int p = t & 1;
        // stage full h into SMEM (L2 loads; never L1-stale)
        hs4[tid] = __ldcg(((const float4*)g_h[p]) + tid);
        float xv = (tg < I_DIM) ? __ldg(&x[(size_t)t * I_DIM + tg]) : 0.f;
        __syncthreads();

        uint64_t h2[8];
        {
            const ulonglong2* hp = (const ulonglong2*)hs4;
#pragma unroll
            for (int j = 0; j < 4; j++) {
                ulonglong2 v = hp[tg + 128 * j];
                h2[2 * j]     = v.x;
                h2[2 * j + 1] = v.y;
            }
        }

        float acc[4];
#pragma unroll
        for (int r = 0; r < 4; r++) {
            float2 seed = make_float2(wr[r] * xv, 0.f);   // xin folded in
            uint64_t a2 = *(uint64_t*)&seed;
#pragma unroll
            for (int j = 0; j < 8; j++) ffma2(a2, w2[r][j], h2[j]);
            float2 f = *(float2*)&a2;
            acc[r] = f.x + f.y;
        }
        // warp-reduce 4 row partials
#pragma unroll
        for (int r = 0; r < 4; r++) {
            float a = acc[r];
#pragma unroll
            for (int s = 16; s > 0; s >>= 1) a += __shfl_xor_sync(0xffffffffu, a, s);
            if (lane == 0) psum2[grp * 4 + r][wig] = a;
        }
        __syncthreads();

        // finalize: thread r handles row r (partials already include xin)
        if (tid < ROWS_PER_BLK) {
            float4 ps = *(const float4*)psum2[tid];
            float v = (ps.x + ps.y) + (ps.z + ps.w);
            v = fminf(15.f, fmaxf(-15.f, v));
            float e = __expf(2.f * v);
            float th = __fdividef(e - 1.f, e + 1.f);
            float hold = ((const float*)hs4)[rbase + tid];
            float hn = 0.5f * hold + 0.5f * th;
            g_h[p ^ 1][rbase + tid] = hn;
            g_states[(size_t)t * R_DIM + rbase + tid] = hn;
        }
        GRID_BARRIER();
    }
#undef GRID_BARRIER
}

// ---------------- fold fc2@fc1 into Wc (50x2048) and bc (50) ----------------
__global__ void wc_kernel(const float* __restrict__ fc1_w,  // [128,2048]
                          const float* __restrict__ fc1_b,  // [128]
                          const float* __restrict__ fc2_w,  // [50,128]
                          const float* __restrict__ fc2_b)  // [50]
{
    const int r = blockIdx.x * 256 + threadIdx.x;  // 0..2047
    const int o = blockIdx.y;                      // 0..49
    float a = 0.0f;
    for (int h = 0; h < H_DIM; h++)
        a += fc2_w[o * H_DIM + h] * fc1_w[(size_t)h * R_DIM + r];
    g_Wc[o * R_DIM + r] = a;
    if (blockIdx.x == 0 && threadIdx.x == 0) {
        float b = fc2_b[o];
        for (int h = 0; h < H_DIM; h++) b += fc2_w[o * H_DIM + h] * fc1_b[h];
        g_bc[o] = b;
    }
}

// ---------------- out = states @ Wc^T + bc ----------------
#define GT 64
#define KT 64
__global__ void __launch_bounds__(256) out_kernel(float* __restrict__ out) {
    __shared__ float s_s[GT][KT + 1];    // pad to kill conflicts
    __shared__ float wc_s[O_DIM][KT];

    const int tid = threadIdx.x;
    const int t0 = blockIdx.x * GT;
    const int r  = tid & 63;
    const int oq = tid >> 6;             // 0..3
    const int OB = 13;                   // ceil(50/4)
    const int o0 = oq * OB;

    float acc[OB];
#pragma unroll
    for (int i = 0; i < OB; i++) acc[i] = 0.0f;

    for (int k0 = 0; k0 < R_DIM; k0 += KT) {
#pragma unroll
        for (int i = 0; i < 4; i++) {
            int idx = tid + 256 * i;
            int rr = idx >> 4, c4 = idx & 15;
            float4 v = ((const float4*)(g_states + (size_t)(t0 + rr) * R_DIM + k0))[c4];
            s_s[rr][4 * c4 + 0] = v.x;
            s_s[rr][4 * c4 + 1] = v.y;
            s_s[rr][4 * c4 + 2] = v.z;
            s_s[rr][4 * c4 + 3] = v.w;
        }
        for (int idx = tid; idx < O_DIM * (KT / 4); idx += 256) {
            int rr = idx >> 4, c4 = idx & 15;
            ((float4*)&wc_s[rr][0])[c4] = ((const float4*)(g_Wc + (size_t)rr * R_DIM + k0))[c4];
        }
        __syncthreads();
#pragma unroll 8
        for (int kk = 0; kk < KT; kk++) {
            float sv = s_s[r][kk];
#pragma unroll
            for (int i = 0; i < OB; i++) {
                int o = o0 + i;
                if (o < O_DIM) acc[i] += sv * wc_s[o][kk];
            }
        }
        __syncthreads();
    }
#pragma unroll
    for (int i = 0; i < OB; i++) {
        int o = o0 + i;
        if (o < O_DIM) out[(size_t)(t0 + r) * O_DIM + o] = acc[i] + g_bc[o];
    }
}

// ---------------- launcher ----------------
extern "C" void kernel_launch(void* const* d_in, const int* in_sizes, int n_in,
                              void* d_out, int out_size) {
    (void)in_sizes; (void)n_in; (void)out_size;
    const float* x     = (const float*)d_in[0];
    const float* Win   = (const float*)d_in[1];
    const float* W     = (const float*)d_in[2];
    const float* fc1_w = (const float*)d_in[3];
    const float* fc1_b = (const float*)d_in[4];
    const float* fc2_w = (const float*)d_in[5];
    const float* fc2_b = (const float*)d_in[6];
    float* out = (float*)d_out;

    wc_kernel<<<dim3(R_DIM / 256, O_DIM), 256>>>(fc1_w, fc1_b, fc2_w, fc2_b);
    esn_kernel<<<NBLK, NTHR>>>(x, Win, W);
    out_kernel<<<S_LEN / GT, 256>>>(out);
}

// round 6
// speedup vs baseline: 1.7015x; 1.7015x over previous
#include <cuda_runtime.h>
#include <math.h>
#include <stdint.h>

#define S_LEN 16384
#define I_DIM 64
#define R_DIM 2048
#define H_DIM 128
#define O_DIM 50
#define NBLK  128
#define ROWS_PER_BLK 16   // 128*16 = 2048
#define NTHR  512
#define GT    128         // timesteps per block in output phase
#define KT    64

// ---------------- device scratch (static; no allocations) ----------------
__device__ float g_h[2][R_DIM];
__device__ float g_states[(size_t)S_LEN * R_DIM];   // 134 MB
__device__ float g_Wc[O_DIM * R_DIM];               // folded fc2@fc1
__device__ float g_bc[O_DIM];                       // folded bias
__device__ unsigned g_count = 0;                    // monotone across replays

// packed f32x2 FMA: d = a*b + d (sm_100+; only reachable via PTX)
__device__ __forceinline__ void ffma2(uint64_t& d, uint64_t a, uint64_t b) {
    asm("fma.rn.f32x2 %0, %1, %2, %0;" : "+l"(d) : "l"(a), "l"(b));
}
__device__ __forceinline__ unsigned ld_acquire_u32(const unsigned* p) {
    unsigned v;
    asm volatile("ld.acquire.gpu.global.u32 %0, [%1];" : "=r"(v) : "l"(p) : "memory");
    return v;
}
__device__ __forceinline__ void red_release_add(unsigned* p, unsigned v) {
    asm volatile("red.release.gpu.global.add.u32 [%0], %1;" :: "l"(p), "r"(v) : "memory");
}

// ---------------- fused persistent kernel ----------------
union SmemU {
    struct { float4 hs4[R_DIM / 4]; float psum[ROWS_PER_BLK][4]; } scan;  // 8.25 KB
    struct { float s[GT][KT + 1]; float wc[O_DIM][KT]; } gemm;            // 46 KB
};

__global__ void __launch_bounds__(NTHR, 1) fused_kernel(
    const float* __restrict__ x,      // [S,64]
    const float* __restrict__ Win,    // [2048,64]
    const float* __restrict__ W,      // [2048,2048]
    const float* __restrict__ fc1_w,  // [128,2048]
    const float* __restrict__ fc1_b,  // [128]
    const float* __restrict__ fc2_w,  // [50,128]
    const float* __restrict__ fc2_b,  // [50]
    float* __restrict__ out)          // [S,50]
{
    __shared__ SmemU sm;

    const int tid  = threadIdx.x;
    const int lane = tid & 31;
    const int wrp  = tid >> 5;          // 0..15
    const int grp  = tid >> 7;          // 0..3
    const int tg   = tid & 127;         // 0..127
    const int wig  = wrp & 3;           // warp-in-group
    const int rbase = blockIdx.x * ROWS_PER_BLK;

    // monotone barrier base (replay-safe; signed-diff compare is wrap-safe)
    unsigned bar_tgt = ld_acquire_u32(&g_count);

#define GBAR()                                                               \
    do {                                                                     \
        __syncthreads();                                                     \
        bar_tgt += NBLK;                                                     \
        if (wrp == 0) {                                                      \
            if (lane == 0) red_release_add(&g_count, 1u);                    \
            unsigned v;                                                      \
            do { v = ld_acquire_u32(&g_count); } while ((int)(v - bar_tgt) < 0); \
        }                                                                    \
        __syncthreads();                                                     \
    } while (0)

    // ---- Phase 0: W slice -> registers; Win fold weights; Wc/bc fold; h0 = 0
    uint64_t w2[4][8];
#pragma unroll
    for (int r = 0; r < 4; r++) {
        const ulonglong2* Wrow = (const ulonglong2*)(W + (size_t)(rbase + grp * 4 + r) * R_DIM);
#pragma unroll
        for (int j = 0; j < 4; j++) {
            ulonglong2 v = Wrow[tg + 128 * j];
            w2[r][2 * j]     = v.x;
            w2[r][2 * j + 1] = v.y;
        }
    }
    float wr[4] = {0.f, 0.f, 0.f, 0.f};
    if (tg < I_DIM) {
#pragma unroll
        for (int r = 0; r < 4; r++)
            wr[r] = __ldg(&Win[(size_t)(rbase + grp * 4 + r) * I_DIM + tg]);
    }
    // Wc fold: this block computes columns [rbase, rbase+16) for all 50 outputs
    for (int idx = tid; idx < O_DIM * ROWS_PER_BLK; idx += NTHR) {
        const int o  = idx >> 4;          // 0..49
        const int rr = idx & 15;
        float a = 0.f;
#pragma unroll 8
        for (int h = 0; h < H_DIM; h++)
            a += __ldg(&fc2_w[o * H_DIM + h]) * __ldg(&fc1_w[(size_t)h * R_DIM + rbase + rr]);
        g_Wc[o * R_DIM + rbase + rr] = a;
    }
    if (blockIdx.x == 0 && tid < O_DIM) {
        float b = __ldg(&fc2_b[tid]);
#pragma unroll 8
        for (int h = 0; h < H_DIM; h++) b += __ldg(&fc2_w[tid * H_DIM + h]) * __ldg(&fc1_b[h]);
        g_bc[tid] = b;
    }
    if (tid < ROWS_PER_BLK) g_h[0][rbase + tid] = 0.0f;

    GBAR();   // h0 + Wc published

    // ---- Phase 1: the scan
    for (int t = 0; t < S_LEN; t++) {
        const int p = t & 1;
        sm.scan.hs4[tid] = __ldcg(((const float4*)g_h[p]) + tid);
        float xv = (tg < I_DIM) ? __ldg(&x[(size_t)t * I_DIM + tg]) : 0.f;
        __syncthreads();

        uint64_t h2[8];
        {
            const ulonglong2* hp = (const ulonglong2*)sm.scan.hs4;
#pragma unroll
            for (int j = 0; j < 4; j++) {
                ulonglong2 v = hp[tg + 128 * j];
                h2[2 * j]     = v.x;
                h2[2 * j + 1] = v.y;
            }
        }

        float acc[4];
#pragma unroll
        for (int r = 0; r < 4; r++) {
            float2 seed = make_float2(wr[r] * xv, 0.f);   // xin folded in
            uint64_t a2 = *(uint64_t*)&seed;
#pragma unroll
            for (int j = 0; j < 8; j++) ffma2(a2, w2[r][j], h2[j]);
            float2 f = *(float2*)&a2;
            acc[r] = f.x + f.y;
        }
#pragma unroll
        for (int r = 0; r < 4; r++) {
            float a = acc[r];
#pragma unroll
            for (int s = 16; s > 0; s >>= 1) a += __shfl_xor_sync(0xffffffffu, a, s);
            if (lane == 0) sm.scan.psum[grp * 4 + r][wig] = a;
        }
        __syncthreads();

        // finalize + barrier fused into warp 0 (others park at bar.sync)
        bar_tgt += NBLK;
        if (wrp == 0) {
            if (lane < ROWS_PER_BLK) {
                const float4 ps = *(const float4*)sm.scan.psum[lane];
                float v = (ps.x + ps.y) + (ps.z + ps.w);
                v = fminf(15.f, fmaxf(-15.f, v));
                const float e  = __expf(2.f * v);
                const float th = __fdividef(e - 1.f, e + 1.f);
                const float hold = ((const float*)sm.scan.hs4)[rbase + lane];
                const float hn = 0.5f * hold + 0.5f * th;
                g_h[p ^ 1][rbase + lane] = hn;
                g_states[(size_t)t * R_DIM + rbase + lane] = hn;
            }
            __syncwarp(0xffffffffu);
            if (lane == 0) red_release_add(&g_count, 1u);
            unsigned v;
            do { v = ld_acquire_u32(&g_count); } while ((int)(v - bar_tgt) < 0);
        }
        __syncthreads();
    }

    GBAR();   // all states published

    // ---- Phase 2: out = states @ Wc^T + bc   (block handles GT timesteps)
    {
        const int t0 = blockIdx.x * GT;
        const int r  = tid & 127;            // row in tile
        const int oq = tid >> 7;             // 0..3
        const int OB = 13;                   // ceil(50/4)
        const int o0 = oq * OB;

        float acc[13];
#pragma unroll
        for (int i = 0; i < 13; i++) acc[i] = 0.0f;

        for (int k0 = 0; k0 < R_DIM; k0 += KT) {
#pragma unroll
            for (int i = 0; i < 4; i++) {
                int idx = tid + NTHR * i;        // 2048 float4 loads
                int rr = idx >> 4, c4 = idx & 15;
                float4 v = __ldcg((const float4*)(g_states + (size_t)(t0 + rr) * R_DIM + k0) + c4);
                sm.gemm.s[rr][4 * c4 + 0] = v.x;
                sm.gemm.s[rr][4 * c4 + 1] = v.y;
                sm.gemm.s[rr][4 * c4 + 2] = v.z;
                sm.gemm.s[rr][4 * c4 + 3] = v.w;
            }
            for (int idx = tid; idx < O_DIM * (KT / 4); idx += NTHR) {
                int rr = idx >> 4, c4 = idx & 15;
                float4 v = __ldcg((const float4*)(g_Wc + (size_t)rr * R_DIM + k0) + c4);
                ((float4*)&sm.gemm.wc[rr][0])[c4] = v;
            }
            __syncthreads();
#pragma unroll 4
            for (int kk = 0; kk < KT; kk++) {
                float sv = sm.gemm.s[r][kk];
#pragma unroll
                for (int i = 0; i < 13; i++) {
                    int o = o0 + i;
                    if (o < O_DIM) acc[i] += sv * sm.gemm.wc[o][kk];
                }
            }
            __syncthreads();
        }
#pragma unroll
        for (int i = 0; i < 13; i++) {
            int o = o0 + i;
            if (o < O_DIM) out[(size_t)(t0 + r) * O_DIM + o] = acc[i] + __ldcg(&g_bc[o]);
        }
    }
#undef GBAR
}

// ---------------- launcher ----------------
extern "C" void kernel_launch(void* const* d_in, const int* in_sizes, int n_in,
                              void* d_out, int out_size) {
    (void)in_sizes; (void)n_in; (void)out_size;
    const float* x     = (const float*)d_in[0];
    const float* Win   = (const float*)d_in[1];
    const float* W     = (const float*)d_in[2];
    const float* fc1_w = (const float*)d_in[3];
    const float* fc1_b = (const float*)d_in[4];
    const float* fc2_w = (const float*)d_in[5];
    const float* fc2_b = (const float*)d_in[6];
    float* out = (float*)d_out;

    fused_kernel<<<NBLK, NTHR>>>(x, Win, W, fc1_w, fc1_b, fc2_w, fc2_b, out);
}

// round 8
// speedup vs baseline: 1.8327x; 1.0771x over previous
#include <cuda_runtime.h>
#include <math.h>
#include <stdint.h>

#define S_LEN 16384
#define I_DIM 64
#define R_DIM 2048
#define H_DIM 128
#define O_DIM 50
#define NBLK  128
#define ROWS_PER_BLK 16   // 128*16 = 2048
#define NTHR  512
#define GT    128         // timesteps per block in output phase
#define KT    64

// ---------------- device scratch (static; no allocations) ----------------
__device__ float g_h[2][R_DIM];
__device__ float g_states[(size_t)S_LEN * R_DIM];   // 134 MB
__device__ float g_Wc[O_DIM * R_DIM];               // folded fc2@fc1
__device__ float g_bc[O_DIM];                       // folded bias
__device__ unsigned g_count = 0;                    // monotone across replays
__device__ unsigned g_base  = 0;                    // snapshot for this launch

// packed f32x2 FMA: d = a*b + d (sm_100+; only reachable via PTX)
__device__ __forceinline__ void ffma2(uint64_t& d, uint64_t a, uint64_t b) {
    asm("fma.rn.f32x2 %0, %1, %2, %0;" : "+l"(d) : "l"(a), "l"(b));
}
__device__ __forceinline__ unsigned ld_acquire_u32(const unsigned* p) {
    unsigned v;
    asm volatile("ld.acquire.gpu.global.u32 %0, [%1];" : "=r"(v) : "l"(p) : "memory");
    return v;
}
__device__ __forceinline__ void red_release_add(unsigned* p, unsigned v) {
    asm volatile("red.release.gpu.global.add.u32 [%0], %1;" :: "l"(p), "r"(v) : "memory");
}
// 16B L2 (cache-global) load as two packed u64
__device__ __forceinline__ void ldcg_v2u64(const void* p, uint64_t& a, uint64_t& b) {
    asm volatile("ld.global.cg.v2.u64 {%0,%1}, [%2];" : "=l"(a), "=l"(b) : "l"(p));
}

// snapshot the barrier counter BEFORE the persistent kernel starts, so every
// block derives identical targets (kills the start-skew deadlock race).
__global__ void prep_kernel() { g_base = g_count; }

// ---------------- fused persistent kernel ----------------
union SmemU {
    float psum[ROWS_PER_BLK][4];                               // scan phase
    struct { float s[GT][KT + 1]; float wc[O_DIM][KT]; } gemm; // 46 KB
};

__global__ void __launch_bounds__(NTHR, 1) fused_kernel(
    const float* __restrict__ x,      // [S,64]
    const float* __restrict__ Win,    // [2048,64]
    const float* __restrict__ W,      // [2048,2048]
    const float* __restrict__ fc1_w,  // [128,2048]
    const float* __restrict__ fc1_b,  // [128]
    const float* __restrict__ fc2_w,  // [50,128]
    const float* __restrict__ fc2_b,  // [50]
    float* __restrict__ out)          // [S,50]
{
    __shared__ SmemU sm;

    const int tid  = threadIdx.x;
    const int lane = tid & 31;
    const int wrp  = tid >> 5;          // 0..15
    const int grp  = tid >> 7;          // 0..3
    const int tg   = tid & 127;         // 0..127
    const int wig  = wrp & 3;           // warp-in-group
    const int rbase = blockIdx.x * ROWS_PER_BLK;

    // identical for all blocks (set by prep_kernel); monotone + wrap-safe
    unsigned bar_tgt = g_base;

#define GBAR()                                                               \
    do {                                                                     \
        __syncthreads();                                                     \
        bar_tgt += NBLK;                                                     \
        if (wrp == 0) {                                                      \
            if (lane == 0) red_release_add(&g_count, 1u);                    \
            unsigned v;                                                      \
            do { v = ld_acquire_u32(&g_count); } while ((int)(v - bar_tgt) < 0); \
        }                                                                    \
        __syncthreads();                                                     \
    } while (0)

    // ---- Phase 0: W slice -> registers; Win fold weights; Wc/bc fold; h0 = 0
    uint64_t w2[4][8];
#pragma unroll
    for (int r = 0; r < 4; r++) {
        const ulonglong2* Wrow = (const ulonglong2*)(W + (size_t)(rbase + grp * 4 + r) * R_DIM);
#pragma unroll
        for (int j = 0; j < 4; j++) {
            ulonglong2 v = Wrow[tg + 128 * j];
            w2[r][2 * j]     = v.x;
            w2[r][2 * j + 1] = v.y;
        }
    }
    float wr[4] = {0.f, 0.f, 0.f, 0.f};
    if (tg < I_DIM) {
#pragma unroll
        for (int r = 0; r < 4; r++)
            wr[r] = __ldg(&Win[(size_t)(rbase + grp * 4 + r) * I_DIM + tg]);
    }
    // Wc fold: this block computes columns [rbase, rbase+16) for all 50 outputs
    for (int idx = tid; idx < O_DIM * ROWS_PER_BLK; idx += NTHR) {
        const int o  = idx >> 4;
        const int rr = idx & 15;
        float a = 0.f;
#pragma unroll 8
        for (int h = 0; h < H_DIM; h++)
            a += __ldg(&fc2_w[o * H_DIM + h]) * __ldg(&fc1_w[(size_t)h * R_DIM + rbase + rr]);
        g_Wc[o * R_DIM + rbase + rr] = a;
    }
    if (blockIdx.x == 0 && tid < O_DIM) {
        float b = __ldg(&fc2_b[tid]);
#pragma unroll 8
        for (int h = 0; h < H_DIM; h++) b += __ldg(&fc2_w[tid * H_DIM + h]) * __ldg(&fc1_b[h]);
        g_bc[tid] = b;
    }
    if (tid < ROWS_PER_BLK) g_h[0][rbase + tid] = 0.0f;

    GBAR();   // h0 + Wc published

    // ---- Phase 1: the scan
    float xv_next = (tg < I_DIM) ? __ldg(&x[tg]) : 0.f;   // x[0]
    float hold_reg = 0.0f;                                 // warp0 lanes<16: own h value

    for (int t = 0; t < S_LEN; t++) {
        const int p = t & 1;
        const float xv = xv_next;
        if (t + 1 < S_LEN && tg < I_DIM) xv_next = __ldg(&x[(size_t)(t + 1) * I_DIM + tg]);

        // h chunks straight from L2 (no SMEM staging)
        uint64_t h2[8];
        {
            const float4* hp = (const float4*)g_h[p];
#pragma unroll
            for (int j = 0; j < 4; j++)
                ldcg_v2u64(hp + tg + 128 * j, h2[2 * j], h2[2 * j + 1]);
        }

        float acc[4];
#pragma unroll
        for (int r = 0; r < 4; r++) {
            float2 seed = make_float2(wr[r] * xv, 0.f);   // xin folded in
            uint64_t a2 = *(uint64_t*)&seed;
#pragma unroll
            for (int j = 0; j < 8; j++) ffma2(a2, w2[r][j], h2[j]);
            float2 f = *(float2*)&a2;
            acc[r] = f.x + f.y;
        }
#pragma unroll
        for (int r = 0; r < 4; r++) {
            float a = acc[r];
#pragma unroll
            for (int s = 16; s > 0; s >>= 1) a += __shfl_xor_sync(0xffffffffu, a, s);
            if (lane == 0) sm.psum[grp * 4 + r][wig] = a;
        }
        __syncthreads();

        // finalize + barrier fused into warp 0 (others park at bar.sync)
        bar_tgt += NBLK;
        if (wrp == 0) {
            float hn = 0.f;
            if (lane < ROWS_PER_BLK) {
                const float4 ps = *(const float4*)sm.psum[lane];
                float v = (ps.x + ps.y) + (ps.z + ps.w);
                v = fminf(15.f, fmaxf(-15.f, v));
                const float e  = __expf(2.f * v);
                const float th = __fdividef(e - 1.f, e + 1.f);
                hn = 0.5f * hold_reg + 0.5f * th;
                hold_reg = hn;
                g_h[p ^ 1][rbase + lane] = hn;         // only this 64B gates the release
            }
            __syncwarp(0xffffffffu);
            if (lane == 0) red_release_add(&g_count, 1u);
            if (lane < ROWS_PER_BLK)                    // ordered by NEXT release; fine
                g_states[(size_t)t * R_DIM + rbase + lane] = hn;
            unsigned v;
            do { v = ld_acquire_u32(&g_count); } while ((int)(v - bar_tgt) < 0);
        }
        __syncthreads();
    }

    GBAR();   // all states published

    // ---- Phase 2: out = states @ Wc^T + bc   (block handles GT timesteps)
    {
        const int t0 = blockIdx.x * GT;
        const int r  = tid & 127;            // row in tile
        const int oq = tid >> 7;             // 0..3
        const int OB = 13;                   // ceil(50/4)
        const int o0 = oq * OB;

        float acc[13];
#pragma unroll
        for (int i = 0; i < 13; i++) acc[i] = 0.0f;

        for (int k0 = 0; k0 < R_DIM; k0 += KT) {
#pragma unroll
            for (int i = 0; i < 4; i++) {
                int idx = tid + NTHR * i;
                int rr = idx >> 4, c4 = idx & 15;
                float4 v = __ldcg((const float4*)(g_states + (size_t)(t0 + rr) * R_DIM + k0) + c4);
                sm.gemm.s[rr][4 * c4 + 0] = v.x;
                sm.gemm.s[rr][4 * c4 + 1] = v.y;
                sm.gemm.s[rr][4 * c4 + 2] = v.z;
                sm.gemm.s[rr][4 * c4 + 3] = v.w;
            }
            for (int idx = tid; idx < O_DIM * (KT / 4); idx += NTHR) {
                int rr = idx >> 4, c4 = idx & 15;
                float4 v = __ldcg((const float4*)(g_Wc + (size_t)rr * R_DIM + k0) + c4);
                ((float4*)&sm.gemm.wc[rr][0])[c4] = v;
            }
            __syncthreads();
#pragma unroll 4
            for (int kk = 0; kk < KT; kk++) {
                float sv = sm.gemm.s[r][kk];
#pragma unroll
                for (int i = 0; i < 13; i++) {
                    int o = o0 + i;
                    if (o < O_DIM) acc[i] += sv * sm.gemm.wc[o][kk];
                }
            }
            __syncthreads();
        }
#pragma unroll
        for (int i = 0; i < 13; i++) {
            int o = o0 + i;
            if (o < O_DIM) out[(size_t)(t0 + r) * O_DIM + o] = acc[i] + __ldcg(&g_bc[o]);
        }
    }
#undef GBAR
}

// ---------------- launcher ----------------
extern "C" void kernel_launch(void* const* d_in, const int* in_sizes, int n_in,
                              void* d_out, int out_size) {
    (void)in_sizes; (void)n_in; (void)out_size;
    const float* x     = (const float*)d_in[0];
    const float* Win   = (const float*)d_in[1];
    const float* W     = (const float*)d_in[2];
    const float* fc1_w = (const float*)d_in[3];
    const float* fc1_b = (const float*)d_in[4];
    const float* fc2_w = (const float*)d_in[5];
    const float* fc2_b = (const float*)d_in[6];
    float* out = (float*)d_out;

    prep_kernel<<<1, 1>>>();
    fused_kernel<<<NBLK, NTHR>>>(x, Win, W, fc1_w, fc1_b, fc2_w, fc2_b, out);
}